// round 2
// baseline (speedup 1.0000x reference)
#include <cuda_runtime.h>

#define F 96
#define CAPN 50240          // node capacity (N = 50000)
#define CAPE 1000000        // edge capacity (E = 899999)
#define THRESH 1024         // rows longer than this go to the heavy kernel
#define FULLM 0xffffffffu

// ---- scratch (__device__ globals; allocation-free rule) ----
__device__ int   g_degi  [CAPN];
__device__ float g_dinv  [CAPN];
__device__ int   g_rowptr[CAPN + 1];
__device__ int   g_cursor[CAPN];
__device__ int   g_srcs  [CAPE];     // CSR-permuted src
__device__ float g_norms [CAPE];     // CSR-permuted edge norm
__device__ int   g_heavy [64];
__device__ int   g_nheavy;
__device__ float g_agg   [CAPN * F]; // aggregated features (reused twice)
__device__ float g_h1    [CAPN * F]; // relu(xagg @ W1 + b1)

// ---------------------------------------------------------------------------
__global__ void init_kernel(int N) {
    int i = blockIdx.x * blockDim.x + threadIdx.x;
    if (i < N) g_degi[i] = 0;
    if (i == 0) g_nheavy = 0;
}

// degree by dst (warp-aggregated for contiguous hub edges)
__global__ void deg_kernel(const int* __restrict__ dst, int E) {
    int e = blockIdx.x * blockDim.x + threadIdx.x;
    bool valid = e < E;
    int d = valid ? dst[e] : -1;
    int d0 = __shfl_sync(FULLM, d, 0);
    unsigned bal = __ballot_sync(FULLM, valid && d == d0);
    if (bal == FULLM) {
        if ((threadIdx.x & 31) == 0) atomicAdd(&g_degi[d0], 32);
    } else if (valid) {
        atomicAdd(&g_degi[d], 1);
    }
}

// single-block exclusive scan of g_degi -> g_rowptr / g_cursor
__global__ void scan_kernel(int N) {
    __shared__ int s[1024];
    const int T = 1024, t = threadIdx.x;
    int chunk = (N + T - 1) / T;
    int beg = t * chunk, end = min(beg + chunk, N);
    int sum = 0;
    for (int i = beg; i < end; i++) sum += g_degi[i];
    s[t] = sum;
    __syncthreads();
    for (int off = 1; off < T; off <<= 1) {   // inclusive Hillis-Steele
        int v = (t >= off) ? s[t - off] : 0;
        __syncthreads();
        if (t >= off) s[t] += v;
        __syncthreads();
    }
    int run = (t == 0) ? 0 : s[t - 1];
    for (int i = beg; i < end; i++) {
        g_rowptr[i] = run;
        g_cursor[i] = run;
        run += g_degi[i];
    }
    if (t == T - 1) g_rowptr[N] = s[T - 1];
}

// dinv + heavy-node list
__global__ void dinv_kernel(int N) {
    int i = blockIdx.x * blockDim.x + threadIdx.x;
    if (i < N) {
        float dg = (float)g_degi[i];
        g_dinv[i] = dg > 0.f ? rsqrtf(fmaxf(dg, 1.f)) : 0.f;
        if (g_degi[i] > THRESH) {
            int k = atomicAdd(&g_nheavy, 1);
            if (k < 64) g_heavy[k] = i;
        }
    }
}

// CSR fill: permute src + precompute norm (warp-aggregated cursor for hub)
__global__ void fill_kernel(const int* __restrict__ src,
                            const int* __restrict__ dst, int E) {
    int e = blockIdx.x * blockDim.x + threadIdx.x;
    bool valid = e < E;
    int s = 0, d = -1;
    float nm = 0.f;
    if (valid) { s = src[e]; d = dst[e]; nm = g_dinv[s] * g_dinv[d]; }
    int d0 = __shfl_sync(FULLM, d, 0);
    unsigned bal = __ballot_sync(FULLM, valid && d == d0);
    int pos = 0;
    if (bal == FULLM) {
        if ((threadIdx.x & 31) == 0) pos = atomicAdd(&g_cursor[d0], 32);
        pos = __shfl_sync(FULLM, pos, 0) + (threadIdx.x & 31);
    } else if (valid) {
        pos = atomicAdd(&g_cursor[d], 1);
    }
    if (valid) { g_srcs[pos] = s; g_norms[pos] = nm; }
}

// ---------------------------------------------------------------------------
// Gather aggregation: g_agg[n] = sum_{e in row n} norm * feat[src]
// one warp per node; 3 features per lane; 32-edge tiles with shfl broadcast
// (heavy rows are zeroed here and accumulated by heavy_kernel afterwards)
// ---------------------------------------------------------------------------
__global__ void gather_kernel(const float* __restrict__ feat, int N) {
    int gw = (blockIdx.x * blockDim.x + threadIdx.x) >> 5;
    int lane = threadIdx.x & 31;
    if (gw >= N) return;
    int beg = g_rowptr[gw], end = g_rowptr[gw + 1];
    int cnt = end - beg;
    float a0 = 0.f, a1 = 0.f, a2 = 0.f;
    if (cnt <= THRESH) {
        for (int t0 = 0; t0 < cnt; t0 += 32) {
            int m = min(32, cnt - t0);
            int sv = 0; float nv = 0.f;
            if (lane < m) {
                sv = g_srcs[beg + t0 + lane];
                nv = g_norms[beg + t0 + lane];
            }
#pragma unroll 4
            for (int j = 0; j < m; j++) {
                int s = __shfl_sync(FULLM, sv, j);
                float nm = __shfl_sync(FULLM, nv, j);
                const float* p = feat + (size_t)s * F;
                a0 = fmaf(nm, __ldg(p + lane),      a0);
                a1 = fmaf(nm, __ldg(p + 32 + lane), a1);
                a2 = fmaf(nm, __ldg(p + 64 + lane), a2);
            }
        }
    }
    float* o = g_agg + (size_t)gw * F;
    o[lane] = a0; o[32 + lane] = a1; o[64 + lane] = a2;
}

// heavy rows (hub): grid-stride warps over the row, atomic accumulate
__global__ void heavy_kernel(const float* __restrict__ feat) {
    int nh = g_nheavy;
    if (nh <= 0) return;
    int lane = threadIdx.x & 31;
    int gw = (blockIdx.x * blockDim.x + threadIdx.x) >> 5;
    int nw = (gridDim.x * blockDim.x) >> 5;
    for (int h = 0; h < nh && h < 64; h++) {
        int node = g_heavy[h];
        int beg = g_rowptr[node], end = g_rowptr[node + 1];
        float a0 = 0.f, a1 = 0.f, a2 = 0.f;
        for (int t0 = beg + gw * 32; t0 < end; t0 += nw * 32) {
            int m = min(32, end - t0);
            int sv = 0; float nv = 0.f;
            if (lane < m) { sv = g_srcs[t0 + lane]; nv = g_norms[t0 + lane]; }
#pragma unroll 4
            for (int j = 0; j < m; j++) {
                int s = __shfl_sync(FULLM, sv, j);
                float nm = __shfl_sync(FULLM, nv, j);
                const float* p = feat + (size_t)s * F;
                a0 = fmaf(nm, __ldg(p + lane),      a0);
                a1 = fmaf(nm, __ldg(p + 32 + lane), a1);
                a2 = fmaf(nm, __ldg(p + 64 + lane), a2);
            }
        }
        float* o = g_agg + (size_t)node * F;
        atomicAdd(o + lane, a0);
        atomicAdd(o + 32 + lane, a1);
        atomicAdd(o + 64 + lane, a2);
    }
}

// ---------------------------------------------------------------------------
// GEMM: out[N,96] = g_agg @ W + b   (optional ReLU on output)
// W in smem; warp computes 4 rows x 3 cols/lane via shfl broadcast
// ---------------------------------------------------------------------------
template <bool RELU>
__global__ void gemm_kernel(const float* __restrict__ W,
                            const float* __restrict__ b,
                            float* __restrict__ out, int N) {
    __shared__ float Ws[F * F];
    for (int i = threadIdx.x; i < F * F; i += blockDim.x) Ws[i] = W[i];
    __syncthreads();

    const int lane = threadIdx.x & 31;
    const int warp = threadIdx.x >> 5;
    int row0 = (blockIdx.x * 8 + warp) * 4;
    if (row0 >= N) return;

    float bb[3];
#pragma unroll
    for (int q = 0; q < 3; q++) bb[q] = b[q * 32 + lane];

    float xr[4][3];
#pragma unroll
    for (int r = 0; r < 4; r++) {
        int row = row0 + r;
#pragma unroll
        for (int q = 0; q < 3; q++)
            xr[r][q] = (row < N) ? g_agg[(size_t)row * F + q * 32 + lane] : 0.f;
    }

    float acc[4][3] = {};
#pragma unroll
    for (int q = 0; q < 3; q++) {
#pragma unroll
        for (int kk = 0; kk < 32; kk++) {
            int k = q * 32 + kk;
            float w0 = Ws[k * F + lane];
            float w1 = Ws[k * F + 32 + lane];
            float w2 = Ws[k * F + 64 + lane];
#pragma unroll
            for (int r = 0; r < 4; r++) {
                float xv = __shfl_sync(FULLM, xr[r][q], kk);
                acc[r][0] = fmaf(xv, w0, acc[r][0]);
                acc[r][1] = fmaf(xv, w1, acc[r][1]);
                acc[r][2] = fmaf(xv, w2, acc[r][2]);
            }
        }
    }

#pragma unroll
    for (int r = 0; r < 4; r++) {
        int row = row0 + r;
        if (row < N) {
#pragma unroll
            for (int q = 0; q < 3; q++) {
                float v = acc[r][q] + bb[q];
                if (RELU) v = fmaxf(v, 0.f);
                out[(size_t)row * F + q * 32 + lane] = v;
            }
        }
    }
}

// ---------------------------------------------------------------------------
// inputs: x, W1, b1, W2a, b2a, W2b, b2b, edge_index[2,E]
// output: concat(mu [N,F], logstd [N,F])
//
// Uses linearity: GCN(x) = (A_norm @ x) @ W + b, so aggregate first,
// then GEMM. Layer-2 GEMMs (mu / logstd) share one aggregation of h1.
// ---------------------------------------------------------------------------
extern "C" void kernel_launch(void* const* d_in, const int* in_sizes, int n_in,
                              void* d_out, int out_size) {
    const float* x   = (const float*)d_in[0];
    const float* W1  = (const float*)d_in[1];
    const float* b1  = (const float*)d_in[2];
    const float* W2a = (const float*)d_in[3];
    const float* b2a = (const float*)d_in[4];
    const float* W2b = (const float*)d_in[5];
    const float* b2b = (const float*)d_in[6];
    const int*   ei  = (const int*)d_in[7];

    const int N = in_sizes[0] / F;
    const int E = in_sizes[7] / 2;
    const int* src = ei;
    const int* dst = ei + E;
    float* out = (float*)d_out;
    const int NF = N * F;

    const int TB = 256;
    int eg = (E + TB - 1) / TB;
    int ng = (N + TB - 1) / TB;
    int wg = (N * 32 + TB - 1) / TB;        // warp-per-node grid
    int gg = (N + 31) / 32;                 // gemm grid (8 warps x 4 rows)

    init_kernel<<<ng, TB>>>(N);
    deg_kernel<<<eg, TB>>>(dst, E);
    scan_kernel<<<1, 1024>>>(N);
    dinv_kernel<<<ng, TB>>>(N);
    fill_kernel<<<eg, TB>>>(src, dst, E);

    gather_kernel<<<wg, TB>>>(x, N);        // xagg -> g_agg
    heavy_kernel<<<128, TB>>>(x);
    gemm_kernel<true><<<gg, TB>>>(W1, b1, g_h1, N);   // h1 = relu(.@W1+b1)

    gather_kernel<<<wg, TB>>>(g_h1, N);     // hagg -> g_agg
    heavy_kernel<<<128, TB>>>(g_h1);
    gemm_kernel<false><<<gg, TB>>>(W2a, b2a, out, N);       // mu
    gemm_kernel<false><<<gg, TB>>>(W2b, b2b, out + NF, N);  // logstd
}